// round 6
// baseline (speedup 1.0000x reference)
#include <cuda_runtime.h>
#include <cuda_bf16.h>

// FeaturesLinear: out[seg] = sum_t (weight[ids[t]] * ratings[t]) + bias
// ids: int32[N], ratings: f32[N], segs: int32[N] (sorted), weight: f32[V,16],
// bias: f32[16], out: f32[batch,16].  N = 819200 (multiple of 32).

#define DIM 16
#define T_PER_THREAD 4   // tokens per thread

__global__ void fl_init_out(float4* __restrict__ out,
                            const float4* __restrict__ bias4,
                            int out_quads) {
    int i = blockIdx.x * blockDim.x + threadIdx.x;
    if (i < out_quads) __stcs(&out[i], __ldg(&bias4[i & 3]));
}

// Lane layout: slot = lane & 3 (which float4 of the 16-float row),
// tokGroup = lane >> 2 (0..7). Thread handles 4 consecutive tokens;
// a warp covers 32 consecutive tokens.
// Metadata is streamed (__ldcs, evict-first) so the per-replay 10MB stream
// does not evict weight-table lines from L2; the 64MB table is then the only
// L2-allocating read traffic and can stay resident across graph replays.
__global__ __launch_bounds__(256)
void fl_main(const int*   __restrict__ ids,
             const float* __restrict__ ratings,
             const int*   __restrict__ segs,
             const float4* __restrict__ weight4,
             float*       __restrict__ out,
             int n) {
    const int lane     = threadIdx.x & 31;
    const int slot     = lane & 3;
    const int tokGroup = lane >> 2;
    const int warpsPerBlock = blockDim.x >> 5;
    const int warpId   = blockIdx.x * warpsPerBlock + (threadIdx.x >> 5);

    const int base = warpId * 32 + tokGroup * T_PER_THREAD;
    if (base >= n) return;

    // ---- metadata for 4 tokens (streaming loads, broadcast across 4 slots)
    int4   idv = __ldcs((const int4*)  (ids     + base));
    float4 rv  = __ldcs((const float4*)(ratings + base));
    int4   sv  = __ldcs((const int4*)  (segs    + base));

    const int   id[4] = {idv.x, idv.y, idv.z, idv.w};
    const float r [4] = {rv.x,  rv.y,  rv.z,  rv.w};
    const int   sg[4] = {sv.x,  sv.y,  sv.z,  sv.w};

    // ---- issue all 4 independent row gathers up front (MLP = 4)
    float4 w[4];
    #pragma unroll
    for (int k = 0; k < T_PER_THREAD; k++)
        w[k] = __ldg(&weight4[(size_t)id[k] * 4 + slot]);

    // ---- thread-serial accumulation with flush on segment boundary
    float4 acc;
    acc.x = w[0].x * r[0]; acc.y = w[0].y * r[0];
    acc.z = w[0].z * r[0]; acc.w = w[0].w * r[0];

    #pragma unroll
    for (int k = 1; k < T_PER_THREAD; k++) {
        if (sg[k] != sg[k - 1]) {
            float* o = out + (size_t)sg[k - 1] * DIM + slot * 4;
            atomicAdd(o + 0, acc.x);
            atomicAdd(o + 1, acc.y);
            atomicAdd(o + 2, acc.z);
            atomicAdd(o + 3, acc.w);
            acc.x = acc.y = acc.z = acc.w = 0.f;
        }
        acc.x += w[k].x * r[k]; acc.y += w[k].y * r[k];
        acc.z += w[k].z * r[k]; acc.w += w[k].w * r[k];
    }

    // ---- cross-lane segmented suffix reduction on trailing partials.
    // Trailing keys are monotone across the warp (sorted segs), so the
    // strided conditional add is an exact segmented reduction.
    int seg = sg[T_PER_THREAD - 1];
    #pragma unroll
    for (int off = 4; off <= 16; off <<= 1) {
        int   oseg = __shfl_down_sync(0xffffffffu, seg, off);
        float ox   = __shfl_down_sync(0xffffffffu, acc.x, off);
        float oy   = __shfl_down_sync(0xffffffffu, acc.y, off);
        float oz   = __shfl_down_sync(0xffffffffu, acc.z, off);
        float ow   = __shfl_down_sync(0xffffffffu, acc.w, off);
        if ((lane + off) < 32 && oseg == seg) {
            acc.x += ox; acc.y += oy; acc.z += oz; acc.w += ow;
        }
    }

    const int  pseg = __shfl_up_sync(0xffffffffu, seg, 4);
    const bool head = (tokGroup == 0) || (pseg != seg);

    if (head) {
        float* o = out + (size_t)seg * DIM + slot * 4;
        atomicAdd(o + 0, acc.x);
        atomicAdd(o + 1, acc.y);
        atomicAdd(o + 2, acc.z);
        atomicAdd(o + 3, acc.w);
    }
}

extern "C" void kernel_launch(void* const* d_in, const int* in_sizes, int n_in,
                              void* d_out, int out_size) {
    const int*   ids     = (const int*)  d_in[0];
    const float* ratings = (const float*)d_in[1];
    const int*   segs    = (const int*)  d_in[2];
    // d_in[3] = batch_size scalar (unused)
    const float* weight  = (const float*)d_in[4];
    const float* bias    = (const float*)d_in[5];
    float*       out     = (float*)d_out;

    const int n = in_sizes[0];

    // Init output with bias (vectorized, streaming stores).
    {
        int quads   = out_size / 4;
        int threads = 256;
        int blocks  = (quads + threads - 1) / threads;
        fl_init_out<<<blocks, threads>>>((float4*)out, (const float4*)bias, quads);
    }

    // Main gather + segmented reduce: 32 tokens per warp, 8 warps per block.
    {
        int warps   = (n + 31) / 32;
        int threads = 256;
        int blocks  = (warps + 7) / 8;
        fl_main<<<blocks, threads>>>(ids, ratings, segs,
                                     (const float4*)weight, out, n);
    }
}

// round 7
// speedup vs baseline: 1.5013x; 1.5013x over previous
#include <cuda_runtime.h>
#include <cuda_bf16.h>

// FeaturesLinear: out[seg] = sum_t (weight[ids[t]] * ratings[t]) + bias
// ids: int32[N], ratings: f32[N], segs: int32[N] (sorted), weight: f32[V,16],
// bias: f32[16], out: f32[batch,16].  N = 819200 (multiple of 32).

#define DIM 16
#define T_PER_THREAD 4   // tokens per thread

// Weight gather: non-coherent load with an L2 evict_last cache-hint policy.
// L1 behavior unchanged (caching); only L2 retention priority is raised so
// the 64MB table survives across graph replays.
__device__ __forceinline__ float4 ldg_evict_last(const float4* p,
                                                 unsigned long long pol) {
    float4 v;
    asm("ld.global.nc.L2::cache_hint.v4.f32 {%0,%1,%2,%3}, [%4], %5;"
        : "=f"(v.x), "=f"(v.y), "=f"(v.z), "=f"(v.w)
        : "l"(p), "l"(pol));
    return v;
}

__global__ void fl_init_out(float4* __restrict__ out,
                            const float4* __restrict__ bias4,
                            int out_quads) {
    int i = blockIdx.x * blockDim.x + threadIdx.x;
    if (i < out_quads) out[i] = __ldg(&bias4[i & 3]);
}

// Lane layout: slot = lane & 3 (which float4 of the 16-float row),
// tokGroup = lane >> 2 (0..7). Thread handles 4 consecutive tokens;
// a warp covers 32 consecutive tokens.
__global__ __launch_bounds__(256)
void fl_main(const int*   __restrict__ ids,
             const float* __restrict__ ratings,
             const int*   __restrict__ segs,
             const float4* __restrict__ weight4,
             float*       __restrict__ out,
             int n) {
    const int lane     = threadIdx.x & 31;
    const int slot     = lane & 3;
    const int tokGroup = lane >> 2;
    const int warpsPerBlock = blockDim.x >> 5;
    const int warpId   = blockIdx.x * warpsPerBlock + (threadIdx.x >> 5);

    const int base = warpId * 32 + tokGroup * T_PER_THREAD;
    if (base >= n) return;

    // L2 evict_last policy for the weight table (created once).
    unsigned long long pol;
    asm("createpolicy.fractional.L2::evict_last.b64 %0, 1.0;" : "=l"(pol));

    // ---- metadata for 4 tokens (default caching path; L1 broadcast hits)
    int4   idv = __ldg((const int4*)  (ids     + base));
    float4 rv  = __ldg((const float4*)(ratings + base));
    int4   sv  = __ldg((const int4*)  (segs    + base));

    const int   id[4] = {idv.x, idv.y, idv.z, idv.w};
    const float r [4] = {rv.x,  rv.y,  rv.z,  rv.w};
    const int   sg[4] = {sv.x,  sv.y,  sv.z,  sv.w};

    // ---- issue all 4 independent row gathers up front (MLP = 4)
    float4 w[4];
    #pragma unroll
    for (int k = 0; k < T_PER_THREAD; k++)
        w[k] = ldg_evict_last(&weight4[(size_t)id[k] * 4 + slot], pol);

    // ---- thread-serial accumulation with flush on segment boundary
    float4 acc;
    acc.x = w[0].x * r[0]; acc.y = w[0].y * r[0];
    acc.z = w[0].z * r[0]; acc.w = w[0].w * r[0];

    #pragma unroll
    for (int k = 1; k < T_PER_THREAD; k++) {
        if (sg[k] != sg[k - 1]) {
            float* o = out + (size_t)sg[k - 1] * DIM + slot * 4;
            atomicAdd(o + 0, acc.x);
            atomicAdd(o + 1, acc.y);
            atomicAdd(o + 2, acc.z);
            atomicAdd(o + 3, acc.w);
            acc.x = acc.y = acc.z = acc.w = 0.f;
        }
        acc.x += w[k].x * r[k]; acc.y += w[k].y * r[k];
        acc.z += w[k].z * r[k]; acc.w += w[k].w * r[k];
    }

    // ---- cross-lane segmented suffix reduction on trailing partials.
    // Trailing keys are monotone across the warp (sorted segs), so the
    // strided conditional add is an exact segmented reduction.
    int seg = sg[T_PER_THREAD - 1];
    #pragma unroll
    for (int off = 4; off <= 16; off <<= 1) {
        int   oseg = __shfl_down_sync(0xffffffffu, seg, off);
        float ox   = __shfl_down_sync(0xffffffffu, acc.x, off);
        float oy   = __shfl_down_sync(0xffffffffu, acc.y, off);
        float oz   = __shfl_down_sync(0xffffffffu, acc.z, off);
        float ow   = __shfl_down_sync(0xffffffffu, acc.w, off);
        if ((lane + off) < 32 && oseg == seg) {
            acc.x += ox; acc.y += oy; acc.z += oz; acc.w += ow;
        }
    }

    const int  pseg = __shfl_up_sync(0xffffffffu, seg, 4);
    const bool head = (tokGroup == 0) || (pseg != seg);

    if (head) {
        float* o = out + (size_t)seg * DIM + slot * 4;
        atomicAdd(o + 0, acc.x);
        atomicAdd(o + 1, acc.y);
        atomicAdd(o + 2, acc.z);
        atomicAdd(o + 3, acc.w);
    }
}

extern "C" void kernel_launch(void* const* d_in, const int* in_sizes, int n_in,
                              void* d_out, int out_size) {
    const int*   ids     = (const int*)  d_in[0];
    const float* ratings = (const float*)d_in[1];
    const int*   segs    = (const int*)  d_in[2];
    // d_in[3] = batch_size scalar (unused)
    const float* weight  = (const float*)d_in[4];
    const float* bias    = (const float*)d_in[5];
    float*       out     = (float*)d_out;

    const int n = in_sizes[0];

    // Init output with bias (vectorized).
    {
        int quads   = out_size / 4;
        int threads = 256;
        int blocks  = (quads + threads - 1) / threads;
        fl_init_out<<<blocks, threads>>>((float4*)out, (const float4*)bias, quads);
    }

    // Main gather + segmented reduce: 32 tokens per warp, 8 warps per block.
    {
        int warps   = (n + 31) / 32;
        int threads = 256;
        int blocks  = (warps + 7) / 8;
        fl_main<<<blocks, threads>>>(ids, ratings, segs,
                                     (const float4*)weight, out, n);
    }
}